// round 6
// baseline (speedup 1.0000x reference)
#include <cuda_runtime.h>
#include <stdint.h>

#define EMB 768
#define VEC (EMB / 4)           // 192 float4 per row
#define F4_PER_LANE (VEC / 32)  // 6
#define WARPS_PER_CTA 4
#define THREADS (WARPS_PER_CTA * 32)
#define GRID 1184               // 148 SMs * 8 CTAs: single persistent wave

// Persistent gather, TWO tokens per warp iteration: 12 independent LDG.128 in
// flight per lane before any store, both next-iteration indices prefetched
// while row data is in flight. Keeps the per-SM L1tex queue saturated so the
// LTS crossbar (the measured structural cap, ~6300 B/cyc combined) never sees
// a drain bubble at token boundaries.
//
// Index dtype (int32 vs int64) detected per warp from odd 32-bit words of the
// index buffer: little-endian int64 storage of vocab ids (< 2^31) has all-zero
// high halves; 32 random int32 vocab ids all being zero ~ (1/50257)^32 ~ 0.
__global__ void __launch_bounds__(THREADS)
embedding_gather(const void* __restrict__ idx_raw,
                 const float4* __restrict__ table,
                 float4* __restrict__ out,
                 int n_tokens) {
    const unsigned int* w = (const unsigned int*)idx_raw;
    int widx = 2 * (threadIdx.x & 31) + 1;
    unsigned int probe = (widx < n_tokens) ? __ldg(w + widx) : 0u;
    bool idx_is_i32 = (__ballot_sync(0xFFFFFFFFu, probe != 0u) != 0u);

    const int* idx32 = (const int*)idx_raw;
    const long long* idx64 = (const long long*)idx_raw;

    int lane = threadIdx.x & 31;
    int warp = blockIdx.x * WARPS_PER_CTA + (threadIdx.x >> 5);
    const int stride = GRID * WARPS_PER_CTA;      // 4736 warps
    // Token pair for this warp: (t, t + stride); advance by 2*stride.
    // n_tokens = 16384 = 3.459 * 4736, so pairs cover [0, 2*stride) fully;
    // the tail loop handles the remaining tokens beyond 2*stride.

    long long i0 = 0, i1 = 0;
    int t = warp;
    bool has0 = (t < n_tokens);
    bool has1 = (t + stride < n_tokens);
    if (has0) i0 = idx_is_i32 ? (long long)__ldg(idx32 + t) : __ldg(idx64 + t);
    if (has1) i1 = idx_is_i32 ? (long long)__ldg(idx32 + t + stride) : __ldg(idx64 + t + stride);

    #pragma unroll 1
    while (has0) {
        const float4* __restrict__ s0 = table + i0 * VEC + lane;
        float4* __restrict__ d0 = out + (long long)t * VEC + lane;

        float4 v0[F4_PER_LANE], v1[F4_PER_LANE];
        #pragma unroll
        for (int j = 0; j < F4_PER_LANE; j++)
            v0[j] = __ldg(s0 + 32 * j);

        if (has1) {
            const float4* __restrict__ s1 = table + i1 * VEC + lane;
            #pragma unroll
            for (int j = 0; j < F4_PER_LANE; j++)
                v1[j] = __ldg(s1 + 32 * j);
        }

        // prefetch next pair's indices while 12 row loads are in flight
        int tn = t + 2 * stride;
        bool nhas0 = (tn < n_tokens);
        bool nhas1 = (tn + stride < n_tokens);
        long long n0 = 0, n1 = 0;
        if (nhas0) n0 = idx_is_i32 ? (long long)__ldg(idx32 + tn) : __ldg(idx64 + tn);
        if (nhas1) n1 = idx_is_i32 ? (long long)__ldg(idx32 + tn + stride) : __ldg(idx64 + tn + stride);

        #pragma unroll
        for (int j = 0; j < F4_PER_LANE; j++)
            __stwt(d0 + 32 * j, v0[j]);

        if (has1) {
            float4* __restrict__ d1 = out + (long long)(t + stride) * VEC + lane;
            #pragma unroll
            for (int j = 0; j < F4_PER_LANE; j++)
                __stwt(d1 + 32 * j, v1[j]);
        }

        t = tn; i0 = n0; i1 = n1; has0 = nhas0; has1 = nhas1;
    }
}

extern "C" void kernel_launch(void* const* d_in, const int* in_sizes, int n_in,
                              void* d_out, int out_size) {
    // indices buffer is the small one; table is 50257*768 elements.
    const void* d_idx;
    const void* d_table;
    int n_tokens;
    if (in_sizes[0] < in_sizes[1]) {
        d_idx = d_in[0];  d_table = d_in[1];  n_tokens = in_sizes[0];
    } else {
        d_idx = d_in[1];  d_table = d_in[0];  n_tokens = in_sizes[1];
    }

    embedding_gather<<<GRID, THREADS>>>(d_idx,
                                        (const float4*)d_table,
                                        (float4*)d_out,
                                        n_tokens);
}

// round 7
// speedup vs baseline: 1.0374x; 1.0374x over previous
#include <cuda_runtime.h>
#include <stdint.h>

#define EMB 768
#define VEC (EMB / 4)           // 192 float4 per row
#define F4_PER_LANE (VEC / 32)  // 6
#define WARPS_PER_CTA 4
#define THREADS (WARPS_PER_CTA * 32)
#define GRID 1184               // 148 SMs * 8 CTAs: single persistent wave

// Persistent warp-per-token gather — the LTS-floor convergence kernel.
//
// Roofline: this problem moves 50.3 MB of table rows + 50.3 MB of output
// across the L2 crossbar; the B300 LTS structural cap (~6300 B/cyc combined,
// path-independent) puts the floor at ~14.6 us. Three architectures (multi-
// wave SIMT, TMA bulk-copy pipeline, persistent SIMT) all measure 14.8 us;
// deeper MLP regresses. This is that optimum: lane l moves float4 elements
// {l, l+32, ..., l+160} (6 independent LDG.128 in flight), next token's index
// prefetched under the row loads, streaming STG.128 so write data doesn't
// evict L2-resident table rows.
//
// Index dtype (int32 vs int64) detected per warp from odd 32-bit words of the
// index buffer: little-endian int64 storage of vocab ids (< 2^31) has all-zero
// high halves; 32 random int32 vocab ids all being zero ~ (1/50257)^32 ~ 0.
__global__ void __launch_bounds__(THREADS)
embedding_gather(const void* __restrict__ idx_raw,
                 const float4* __restrict__ table,
                 float4* __restrict__ out,
                 int n_tokens) {
    const unsigned int* w = (const unsigned int*)idx_raw;
    int widx = 2 * (threadIdx.x & 31) + 1;
    unsigned int probe = (widx < n_tokens) ? __ldg(w + widx) : 0u;
    bool idx_is_i32 = (__ballot_sync(0xFFFFFFFFu, probe != 0u) != 0u);

    const int* idx32 = (const int*)idx_raw;
    const long long* idx64 = (const long long*)idx_raw;

    int lane = threadIdx.x & 31;
    int warp = blockIdx.x * WARPS_PER_CTA + (threadIdx.x >> 5);
    const int stride = GRID * WARPS_PER_CTA;

    if (warp >= n_tokens) return;

    long long idx = idx_is_i32 ? (long long)__ldg(idx32 + warp)
                               : __ldg(idx64 + warp);

    #pragma unroll 1
    for (int t = warp; t < n_tokens; t += stride) {
        const float4* __restrict__ src = table + idx * VEC + lane;
        float4* __restrict__ dst = out + (long long)t * VEC + lane;

        float4 v[F4_PER_LANE];
        #pragma unroll
        for (int j = 0; j < F4_PER_LANE; j++)
            v[j] = __ldg(src + 32 * j);

        int tn = t + stride;
        if (tn < n_tokens) {
            idx = idx_is_i32 ? (long long)__ldg(idx32 + tn)
                             : __ldg(idx64 + tn);
        }

        #pragma unroll
        for (int j = 0; j < F4_PER_LANE; j++)
            __stwt(dst + 32 * j, v[j]);
    }
}

extern "C" void kernel_launch(void* const* d_in, const int* in_sizes, int n_in,
                              void* d_out, int out_size) {
    // indices buffer is the small one; table is 50257*768 elements.
    const void* d_idx;
    const void* d_table;
    int n_tokens;
    if (in_sizes[0] < in_sizes[1]) {
        d_idx = d_in[0];  d_table = d_in[1];  n_tokens = in_sizes[0];
    } else {
        d_idx = d_in[1];  d_table = d_in[0];  n_tokens = in_sizes[1];
    }

    embedding_gather<<<GRID, THREADS>>>(d_idx,
                                        (const float4*)d_table,
                                        (float4*)d_out,
                                        n_tokens);
}